// round 1
// baseline (speedup 1.0000x reference)
#include <cuda_runtime.h>
#include <math.h>

// Problem constants
#define T_TOKENS 4096
#define H_DIM    2048
#define NCAT     5120          // 1024 (imp) + 2048 (r) + 2048 (u)
#define E_EXP    8
#define CAP      1536

// Scratch (device globals: allocation-free)
__device__ float g_hidden[(size_t)T_TOKENS * NCAT];   // relu(x@[Wi1|Wr1|Wu1]+b)
__device__ int   g_top1[T_TOKENS];
__device__ int   g_top2[T_TOKENS];
__device__ float g_p1[T_TOKENS];
__device__ float g_p2[T_TOKENS];
__device__ int   g_mask[T_TOKENS];
__device__ int   g_flag[E_EXP];

// ---------------------------------------------------------------------------
// Fused GEMM: out[4096][5120] = relu(X[4096][2048] @ Wcat[2048][5120] + bcat)
// Column tiles 0..7 -> Wi1 (ld 1024), 8..23 -> Wr1 (ld 2048), 24..39 -> Wu1.
// 128x128x8 tiles, 256 threads, 8x8 accum per thread, fp32.
// ---------------------------------------------------------------------------
__global__ __launch_bounds__(256, 2)
void gemm_relu_kernel(const float* __restrict__ X,
                      const float* __restrict__ Wi1, const float* __restrict__ bi1,
                      const float* __restrict__ Wr1, const float* __restrict__ br1,
                      const float* __restrict__ Wu1, const float* __restrict__ bu1)
{
    const int colTile = blockIdx.x * 128;
    const int rowTile = blockIdx.y * 128;

    const float* W; const float* bias; int ldw; int wcol;
    if (colTile < 1024)      { W = Wi1; bias = bi1; ldw = 1024; wcol = colTile; }
    else if (colTile < 3072) { W = Wr1; bias = br1; ldw = 2048; wcol = colTile - 1024; }
    else                     { W = Wu1; bias = bu1; ldw = 2048; wcol = colTile - 3072; }

    __shared__ float As[8][128];
    __shared__ float Bs[8][128];

    const int tid = threadIdx.x;
    const int ty = tid >> 4;          // 0..15 : row group
    const int tx = tid & 15;          // 0..15 : col group

    const int aRow = tid >> 1;        // 0..127
    const int aCol = (tid & 1) << 2;  // 0 or 4
    const int bRow = tid >> 5;        // 0..7
    const int bCol = (tid & 31) << 2; // 0..124

    const float* Aptr = X + (size_t)(rowTile + aRow) * H_DIM + aCol;
    const float* Bptr = W + (size_t)bRow * ldw + wcol + bCol;

    float acc[8][8];
    #pragma unroll
    for (int i = 0; i < 8; i++)
        #pragma unroll
        for (int j = 0; j < 8; j++) acc[i][j] = 0.f;

    for (int k0 = 0; k0 < H_DIM; k0 += 8) {
        float4 av = *(const float4*)(Aptr + k0);
        float4 bv = *(const float4*)(Bptr + (size_t)k0 * ldw);
        __syncthreads();
        As[aCol + 0][aRow] = av.x;
        As[aCol + 1][aRow] = av.y;
        As[aCol + 2][aRow] = av.z;
        As[aCol + 3][aRow] = av.w;
        *(float4*)&Bs[bRow][bCol] = bv;
        __syncthreads();
        #pragma unroll
        for (int kk = 0; kk < 8; kk++) {
            float a[8], b[8];
            *(float4*)(a)     = *(const float4*)&As[kk][ty * 8];
            *(float4*)(a + 4) = *(const float4*)&As[kk][ty * 8 + 4];
            *(float4*)(b)     = *(const float4*)&Bs[kk][tx * 8];
            *(float4*)(b + 4) = *(const float4*)&Bs[kk][tx * 8 + 4];
            #pragma unroll
            for (int i = 0; i < 8; i++)
                #pragma unroll
                for (int j = 0; j < 8; j++)
                    acc[i][j] += a[i] * b[j];
        }
    }

    float bvals[8];
    #pragma unroll
    for (int j = 0; j < 8; j++) bvals[j] = bias[wcol + tx * 8 + j];

    #pragma unroll
    for (int i = 0; i < 8; i++) {
        int row = rowTile + ty * 8 + i;
        float* op = g_hidden + (size_t)row * NCAT + colTile + tx * 8;
        float4 v0, v1;
        v0.x = fmaxf(acc[i][0] + bvals[0], 0.f);
        v0.y = fmaxf(acc[i][1] + bvals[1], 0.f);
        v0.z = fmaxf(acc[i][2] + bvals[2], 0.f);
        v0.w = fmaxf(acc[i][3] + bvals[3], 0.f);
        v1.x = fmaxf(acc[i][4] + bvals[4], 0.f);
        v1.y = fmaxf(acc[i][5] + bvals[5], 0.f);
        v1.z = fmaxf(acc[i][6] + bvals[6], 0.f);
        v1.w = fmaxf(acc[i][7] + bvals[7], 0.f);
        *(float4*)(op)     = v0;
        *(float4*)(op + 4) = v1;
    }
}

// ---------------------------------------------------------------------------
// Per-token router: importance, branch-select logits, softmax, stable top-2.
// One block (256 threads) per token.
// ---------------------------------------------------------------------------
__global__ __launch_bounds__(256)
void router_kernel(const float* __restrict__ Wi2, const float* __restrict__ bi2,
                   const float* __restrict__ Wr2, const float* __restrict__ br2,
                   const float* __restrict__ Wu2, const float* __restrict__ bu2,
                   float* __restrict__ probs_out, float* __restrict__ imp_out)
{
    const int t = blockIdx.x;
    const int tid = threadIdx.x;
    const float* hrow = g_hidden + (size_t)t * NCAT;

    __shared__ float red[256];
    float s = 0.f;
    for (int k = tid; k < 1024; k += 256) s += hrow[k] * Wi2[k];
    red[tid] = s;
    __syncthreads();
    for (int off = 128; off > 0; off >>= 1) {
        if (tid < off) red[tid] += red[tid + off];
        __syncthreads();
    }

    __shared__ float sh_imp;
    __shared__ int sh_mask;
    if (tid == 0) {
        float z = red[0] + bi2[0];
        float imp = 1.f / (1.f + expf(-z));
        sh_imp = imp;
        sh_mask = (imp > 0.5f) ? 1 : 0;
    }
    __syncthreads();

    const int mask = sh_mask;
    const float* h2 = hrow + (mask ? 1024 : 3072);
    const float* W2 = mask ? Wr2 : Wu2;
    const float* b2 = mask ? br2 : bu2;

    const int w = tid >> 5, lane = tid & 31;
    float acc = 0.f;
    for (int k = lane; k < 2048; k += 32) acc += h2[k] * W2[k * 8 + w];
    #pragma unroll
    for (int off = 16; off > 0; off >>= 1)
        acc += __shfl_down_sync(0xffffffffu, acc, off);

    __shared__ float logits[8];
    if (lane == 0) logits[w] = acc + b2[w];
    __syncthreads();

    if (tid == 0) {
        float mx = logits[0];
        #pragma unroll
        for (int e = 1; e < 8; e++) mx = fmaxf(mx, logits[e]);
        float ex[8], ssum = 0.f;
        #pragma unroll
        for (int e = 0; e < 8; e++) { ex[e] = expf(logits[e] - mx); ssum += ex[e]; }
        float p[8];
        #pragma unroll
        for (int e = 0; e < 8; e++) {
            p[e] = ex[e] / ssum;
            probs_out[t * 8 + e] = p[e];
        }
        imp_out[t] = sh_imp;
        // stable top-2 (ties -> lower index, matching lax.top_k)
        int i1 = 0;
        #pragma unroll
        for (int e = 1; e < 8; e++) if (p[e] > p[i1]) i1 = e;
        int i2 = (i1 == 0) ? 1 : 0;
        #pragma unroll
        for (int e = 0; e < 8; e++) if (e != i1 && p[e] > p[i2]) i2 = e;
        float p1 = p[i1], p2 = p[i2];
        float inv = 1.f / (p1 + p2);
        g_top1[t] = i1; g_top2[t] = i2;
        g_p1[t] = p1 * inv; g_p2[t] = p2 * inv;
        g_mask[t] = mask;
    }
}

// ---------------------------------------------------------------------------
// Single-block reduction: rppe, imp_sum, top-1 occupancy flags, aux_loss.
// ---------------------------------------------------------------------------
__global__ __launch_bounds__(256)
void reduce_aux_kernel(const float* __restrict__ probs, float* __restrict__ aux_out)
{
    const int tid = threadIdx.x;
    double pr[8], im[8];
    #pragma unroll
    for (int e = 0; e < 8; e++) { pr[e] = 0.0; im[e] = 0.0; }

    __shared__ int flags[8];
    if (tid < 8) flags[tid] = 0;
    __syncthreads();

    for (int t = tid; t < T_TOKENS; t += 256) {
        const int m = g_mask[t];
        atomicOr(&flags[g_top1[t]], 1);
        #pragma unroll
        for (int e = 0; e < 8; e++) {
            float p = probs[t * 8 + e];
            pr[e] += (double)p;
            if (m) im[e] += (double)p;
        }
    }
    // warp reduce
    #pragma unroll
    for (int e = 0; e < 8; e++) {
        #pragma unroll
        for (int off = 16; off > 0; off >>= 1) {
            pr[e] += __shfl_down_sync(0xffffffffu, pr[e], off);
            im[e] += __shfl_down_sync(0xffffffffu, im[e], off);
        }
    }
    __shared__ double spr[8][8], sim[8][8];
    const int w = tid >> 5, lane = tid & 31;
    if (lane == 0) {
        #pragma unroll
        for (int e = 0; e < 8; e++) { spr[w][e] = pr[e]; sim[w][e] = im[e]; }
    }
    __syncthreads();

    if (tid == 0) {
        double P[8], I[8];
        #pragma unroll
        for (int e = 0; e < 8; e++) {
            P[e] = 0.0; I[e] = 0.0;
            for (int ww = 0; ww < 8; ww++) { P[e] += spr[ww][e]; I[e] += sim[ww][e]; }
        }
        double el = 0.0;
        for (int e = 0; e < 8; e++) {
            double r = P[e] / (double)T_TOKENS;
            el += r * log(r * 8.0 + 1e-9);
        }
        double ssum = 0.0;
        for (int e = 0; e < 8; e++) { I[e] += 1e-9; ssum += I[e]; }
        double ie = 0.0;
        for (int e = 0; e < 8; e++) {
            double q = I[e] / ssum;
            ie -= q * log(q + 1e-9);
        }
        double aux = el - 0.1 * (ie / log(8.0));
        aux_out[0] = (float)aux;
        for (int e = 0; e < 8; e++) g_flag[e] = flags[e];
    }
}

// ---------------------------------------------------------------------------
// Scatter into memset-zeroed disp/comb. 4 writes per token, no collisions.
// ---------------------------------------------------------------------------
__global__ __launch_bounds__(256)
void scatter_kernel(float* __restrict__ disp, float* __restrict__ comb)
{
    const int t = blockIdx.x * blockDim.x + threadIdx.x;
    if (t >= T_TOKENS) return;
    const int e1 = g_top1[t], e2 = g_top2[t];
    const int pos2 = g_flag[e2];     // 1 if expert e2 is some token's top-1
    const size_t base = (size_t)t * (E_EXP * CAP);
    disp[base + (size_t)e1 * CAP] = 1.0f;
    comb[base + (size_t)e1 * CAP] = g_p1[t];
    disp[base + (size_t)e2 * CAP + pos2] = 1.0f;
    comb[base + (size_t)e2 * CAP + pos2] = g_p2[t];
}

// ---------------------------------------------------------------------------
extern "C" void kernel_launch(void* const* d_in, const int* in_sizes, int n_in,
                              void* d_out, int out_size)
{
    const float* x   = (const float*)d_in[0];
    const float* Wi1 = (const float*)d_in[1];
    const float* bi1 = (const float*)d_in[2];
    const float* Wi2 = (const float*)d_in[3];
    const float* bi2 = (const float*)d_in[4];
    const float* Wr1 = (const float*)d_in[5];
    const float* br1 = (const float*)d_in[6];
    const float* Wr2 = (const float*)d_in[7];
    const float* br2 = (const float*)d_in[8];
    const float* Wu1 = (const float*)d_in[9];
    const float* bu1 = (const float*)d_in[10];
    const float* Wu2 = (const float*)d_in[11];
    const float* bu2 = (const float*)d_in[12];

    float* out = (float*)d_out;
    const size_t dispN = (size_t)T_TOKENS * E_EXP * CAP;   // 50,331,648
    float* disp  = out;
    float* comb  = out + dispN;
    float* probs = out + 2 * dispN;
    float* aux   = probs + (size_t)T_TOKENS * E_EXP;
    float* imp   = aux + 1;

    // Zero the whole output (disp/comb are sparse; rest overwritten anyway).
    cudaMemsetAsync(d_out, 0, (size_t)out_size * sizeof(float));

    dim3 ggrid(NCAT / 128, T_TOKENS / 128);   // 40 x 32
    gemm_relu_kernel<<<ggrid, 256>>>(x, Wi1, bi1, Wr1, br1, Wu1, bu1);
    router_kernel<<<T_TOKENS, 256>>>(Wi2, bi2, Wr2, br2, Wu2, bu2, probs, imp);
    reduce_aux_kernel<<<1, 256>>>(probs, aux);
    scatter_kernel<<<(T_TOKENS + 255) / 256, 256>>>(disp, comb);
}

// round 7
// speedup vs baseline: 1.3852x; 1.3852x over previous
#include <cuda_runtime.h>
#include <math.h>
#include <stdint.h>

// Problem constants
#define T_TOKENS 4096
#define H_DIM    2048
#define E_EXP    8
#define CAP      1536

// Scratch (device globals: allocation-free)
__device__ float g_hidI[(size_t)T_TOKENS * 1024];    // relu(x@Wi1+bi1)
__device__ float g_hid2[(size_t)T_TOKENS * 2048];    // relu(x@W{r,u}1+b) per token
__device__ int   g_top1[T_TOKENS];
__device__ int   g_top2[T_TOKENS];
__device__ float g_p1[T_TOKENS];
__device__ float g_p2[T_TOKENS];
__device__ int   g_mask[T_TOKENS];
__device__ int   g_flag[E_EXP];
__device__ int   g_listR[T_TOKENS];
__device__ int   g_listU[T_TOKENS];
__device__ int   g_cntR;
__device__ int   g_cntU;

// ---------------------------------------------------------------------------
// GEMM-1: g_hidI[4096][1024] = relu(X @ Wi1 + bi1)
// 128x128x8 tiles, 256 threads, 8x8 accum per thread, fp32.
// Also zeroes the compaction counters (runs before imp_kernel in stream order).
// ---------------------------------------------------------------------------
__global__ __launch_bounds__(256, 2)
void gemm1_kernel(const float* __restrict__ X,
                  const float* __restrict__ Wi1, const float* __restrict__ bi1)
{
    if (blockIdx.x == 0 && blockIdx.y == 0 && threadIdx.x == 0) {
        g_cntR = 0; g_cntU = 0;
    }

    const int colTile = blockIdx.x * 128;
    const int rowTile = blockIdx.y * 128;
    const int ldw = 1024;

    __shared__ float As[8][128];
    __shared__ float Bs[8][128];

    const int tid = threadIdx.x;
    const int ty = tid >> 4;
    const int tx = tid & 15;
    const int aRow = tid >> 1;
    const int aCol = (tid & 1) << 2;
    const int bRow = tid >> 5;
    const int bCol = (tid & 31) << 2;

    const float* Aptr = X + (size_t)(rowTile + aRow) * H_DIM + aCol;
    const float* Bptr = Wi1 + (size_t)bRow * ldw + colTile + bCol;

    float acc[8][8];
    #pragma unroll
    for (int i = 0; i < 8; i++)
        #pragma unroll
        for (int j = 0; j < 8; j++) acc[i][j] = 0.f;

    for (int k0 = 0; k0 < H_DIM; k0 += 8) {
        float4 av = *(const float4*)(Aptr + k0);
        float4 bv = *(const float4*)(Bptr + (size_t)k0 * ldw);
        __syncthreads();
        As[aCol + 0][aRow] = av.x;
        As[aCol + 1][aRow] = av.y;
        As[aCol + 2][aRow] = av.z;
        As[aCol + 3][aRow] = av.w;
        *(float4*)&Bs[bRow][bCol] = bv;
        __syncthreads();
        #pragma unroll
        for (int kk = 0; kk < 8; kk++) {
            float a[8], b[8];
            *(float4*)(a)     = *(const float4*)&As[kk][ty * 8];
            *(float4*)(a + 4) = *(const float4*)&As[kk][ty * 8 + 4];
            *(float4*)(b)     = *(const float4*)&Bs[kk][tx * 8];
            *(float4*)(b + 4) = *(const float4*)&Bs[kk][tx * 8 + 4];
            #pragma unroll
            for (int i = 0; i < 8; i++)
                #pragma unroll
                for (int j = 0; j < 8; j++)
                    acc[i][j] += a[i] * b[j];
        }
    }

    float bvals[8];
    #pragma unroll
    for (int j = 0; j < 8; j++) bvals[j] = bi1[colTile + tx * 8 + j];

    #pragma unroll
    for (int i = 0; i < 8; i++) {
        int row = rowTile + ty * 8 + i;
        float* op = g_hidI + (size_t)row * 1024 + colTile + tx * 8;
        float4 v0, v1;
        v0.x = fmaxf(acc[i][0] + bvals[0], 0.f);
        v0.y = fmaxf(acc[i][1] + bvals[1], 0.f);
        v0.z = fmaxf(acc[i][2] + bvals[2], 0.f);
        v0.w = fmaxf(acc[i][3] + bvals[3], 0.f);
        v1.x = fmaxf(acc[i][4] + bvals[4], 0.f);
        v1.y = fmaxf(acc[i][5] + bvals[5], 0.f);
        v1.z = fmaxf(acc[i][6] + bvals[6], 0.f);
        v1.w = fmaxf(acc[i][7] + bvals[7], 0.f);
        *(float4*)(op)     = v0;
        *(float4*)(op + 4) = v1;
    }
}

// ---------------------------------------------------------------------------
// Importance: sigmoid(hidI @ Wi2 + bi2), threshold mask, token compaction.
// One block (128 threads) per token.
// ---------------------------------------------------------------------------
__global__ __launch_bounds__(128)
void imp_kernel(const float* __restrict__ Wi2, const float* __restrict__ bi2,
                float* __restrict__ imp_out)
{
    const int t = blockIdx.x;
    const int tid = threadIdx.x;
    const float* hrow = g_hidI + (size_t)t * 1024;

    float s = 0.f;
    #pragma unroll
    for (int k = tid; k < 1024; k += 128) s += hrow[k] * Wi2[k];
    #pragma unroll
    for (int off = 16; off > 0; off >>= 1)
        s += __shfl_down_sync(0xffffffffu, s, off);

    __shared__ float warp_s[4];
    if ((tid & 31) == 0) warp_s[tid >> 5] = s;
    __syncthreads();

    if (tid == 0) {
        float z = warp_s[0] + warp_s[1] + warp_s[2] + warp_s[3] + bi2[0];
        float imp = 1.f / (1.f + expf(-z));
        imp_out[t] = imp;
        int m = (imp > 0.5f) ? 1 : 0;
        g_mask[t] = m;
        if (m) { int p = atomicAdd(&g_cntR, 1); g_listR[p] = t; }
        else   { int p = atomicAdd(&g_cntU, 1); g_listU[p] = t; }
    }
}

// ---------------------------------------------------------------------------
// GEMM-2 (branch): for compacted token list, h = relu(X[tok] @ W1 + b1),
// stored token-indexed into g_hid2. Fixed grid; tiles beyond count exit.
// ---------------------------------------------------------------------------
__global__ __launch_bounds__(256, 2)
void gemm2_kernel(const float* __restrict__ X,
                  const float* __restrict__ W1, const float* __restrict__ b1,
                  const int* __restrict__ list, const int* __restrict__ countp)
{
    const int count = *countp;
    const int rowTile = blockIdx.y * 128;
    if (rowTile >= count) return;
    const int colTile = blockIdx.x * 128;
    const int ldw = 2048;

    __shared__ float As[8][128];
    __shared__ float Bs[8][128];
    __shared__ int   toks[128];

    const int tid = threadIdx.x;
    const int ty = tid >> 4;
    const int tx = tid & 15;
    const int aRow = tid >> 1;
    const int aCol = (tid & 1) << 2;
    const int bRow = tid >> 5;
    const int bCol = (tid & 31) << 2;

    if (tid < 128) {
        int r = rowTile + tid;
        toks[tid] = list[r < count ? r : count - 1];
    }
    __syncthreads();

    const float* Aptr = X + (size_t)toks[aRow] * H_DIM + aCol;
    const float* Bptr = W1 + (size_t)bRow * ldw + colTile + bCol;

    float acc[8][8];
    #pragma unroll
    for (int i = 0; i < 8; i++)
        #pragma unroll
        for (int j = 0; j < 8; j++) acc[i][j] = 0.f;

    for (int k0 = 0; k0 < H_DIM; k0 += 8) {
        float4 av = *(const float4*)(Aptr + k0);
        float4 bv = *(const float4*)(Bptr + (size_t)k0 * ldw);
        __syncthreads();
        As[aCol + 0][aRow] = av.x;
        As[aCol + 1][aRow] = av.y;
        As[aCol + 2][aRow] = av.z;
        As[aCol + 3][aRow] = av.w;
        *(float4*)&Bs[bRow][bCol] = bv;
        __syncthreads();
        #pragma unroll
        for (int kk = 0; kk < 8; kk++) {
            float a[8], b[8];
            *(float4*)(a)     = *(const float4*)&As[kk][ty * 8];
            *(float4*)(a + 4) = *(const float4*)&As[kk][ty * 8 + 4];
            *(float4*)(b)     = *(const float4*)&Bs[kk][tx * 8];
            *(float4*)(b + 4) = *(const float4*)&Bs[kk][tx * 8 + 4];
            #pragma unroll
            for (int i = 0; i < 8; i++)
                #pragma unroll
                for (int j = 0; j < 8; j++)
                    acc[i][j] += a[i] * b[j];
        }
    }

    float bvals[8];
    #pragma unroll
    for (int j = 0; j < 8; j++) bvals[j] = b1[colTile + tx * 8 + j];

    #pragma unroll
    for (int i = 0; i < 8; i++) {
        int r = rowTile + ty * 8 + i;
        if (r >= count) continue;
        float* op = g_hid2 + (size_t)toks[ty * 8 + i] * 2048 + colTile + tx * 8;
        float4 v0, v1;
        v0.x = fmaxf(acc[i][0] + bvals[0], 0.f);
        v0.y = fmaxf(acc[i][1] + bvals[1], 0.f);
        v0.z = fmaxf(acc[i][2] + bvals[2], 0.f);
        v0.w = fmaxf(acc[i][3] + bvals[3], 0.f);
        v1.x = fmaxf(acc[i][4] + bvals[4], 0.f);
        v1.y = fmaxf(acc[i][5] + bvals[5], 0.f);
        v1.z = fmaxf(acc[i][6] + bvals[6], 0.f);
        v1.w = fmaxf(acc[i][7] + bvals[7], 0.f);
        *(float4*)(op)     = v0;
        *(float4*)(op + 4) = v1;
    }
}

// ---------------------------------------------------------------------------
// Router: per-token logits (branch-selected W2), softmax, stable top-2.
// ---------------------------------------------------------------------------
__global__ __launch_bounds__(256)
void router_kernel(const float* __restrict__ Wr2, const float* __restrict__ br2,
                   const float* __restrict__ Wu2, const float* __restrict__ bu2,
                   float* __restrict__ probs_out)
{
    const int t = blockIdx.x;
    const int tid = threadIdx.x;
    const int mask = g_mask[t];
    const float* h2 = g_hid2 + (size_t)t * 2048;
    const float* W2 = mask ? Wr2 : Wu2;
    const float* b2 = mask ? br2 : bu2;

    const int w = tid >> 5, lane = tid & 31;
    float acc = 0.f;
    for (int k = lane; k < 2048; k += 32) acc += h2[k] * W2[k * 8 + w];
    #pragma unroll
    for (int off = 16; off > 0; off >>= 1)
        acc += __shfl_down_sync(0xffffffffu, acc, off);

    __shared__ float logits[8];
    if (lane == 0) logits[w] = acc + b2[w];
    __syncthreads();

    if (tid == 0) {
        float mx = logits[0];
        #pragma unroll
        for (int e = 1; e < 8; e++) mx = fmaxf(mx, logits[e]);
        float ex[8], ssum = 0.f;
        #pragma unroll
        for (int e = 0; e < 8; e++) { ex[e] = expf(logits[e] - mx); ssum += ex[e]; }
        float p[8];
        #pragma unroll
        for (int e = 0; e < 8; e++) {
            p[e] = ex[e] / ssum;
            probs_out[t * 8 + e] = p[e];
        }
        int i1 = 0;
        #pragma unroll
        for (int e = 1; e < 8; e++) if (p[e] > p[i1]) i1 = e;
        int i2 = (i1 == 0) ? 1 : 0;
        #pragma unroll
        for (int e = 0; e < 8; e++) if (e != i1 && p[e] > p[i2]) i2 = e;
        float p1 = p[i1], p2 = p[i2];
        float inv = 1.f / (p1 + p2);
        g_top1[t] = i1; g_top2[t] = i2;
        g_p1[t] = p1 * inv; g_p2[t] = p2 * inv;
    }
}

// ---------------------------------------------------------------------------
// Single-block reduction: rppe, imp_sum, top-1 occupancy flags, aux_loss.
// ---------------------------------------------------------------------------
__global__ __launch_bounds__(256)
void reduce_aux_kernel(const float* __restrict__ probs, float* __restrict__ aux_out)
{
    const int tid = threadIdx.x;
    double pr[8], im[8];
    #pragma unroll
    for (int e = 0; e < 8; e++) { pr[e] = 0.0; im[e] = 0.0; }

    __shared__ int flags[8];
    if (tid < 8) flags[tid] = 0;
    __syncthreads();

    for (int t = tid; t < T_TOKENS; t += 256) {
        const int m = g_mask[t];
        atomicOr(&flags[g_top1[t]], 1);
        #pragma unroll
        for (int e = 0; e < 8; e++) {
            float p = probs[t * 8 + e];
            pr[e] += (double)p;
            if (m) im[e] += (double)p;
        }
    }
    #pragma unroll
    for (int e = 0; e < 8; e++) {
        #pragma unroll
        for (int off = 16; off > 0; off >>= 1) {
            pr[e] += __shfl_down_sync(0xffffffffu, pr[e], off);
            im[e] += __shfl_down_sync(0xffffffffu, im[e], off);
        }
    }
    __shared__ double spr[8][8], sim[8][8];
    const int w = tid >> 5, lane = tid & 31;
    if (lane == 0) {
        #pragma unroll
        for (int e = 0; e < 8; e++) { spr[w][e] = pr[e]; sim[w][e] = im[e]; }
    }
    __syncthreads();

    if (tid == 0) {
        double P[8], I[8];
        #pragma unroll
        for (int e = 0; e < 8; e++) {
            P[e] = 0.0; I[e] = 0.0;
            for (int ww = 0; ww < 8; ww++) { P[e] += spr[ww][e]; I[e] += sim[ww][e]; }
        }
        double el = 0.0;
        for (int e = 0; e < 8; e++) {
            double r = P[e] / (double)T_TOKENS;
            el += r * log(r * 8.0 + 1e-9);
        }
        double ssum = 0.0;
        for (int e = 0; e < 8; e++) { I[e] += 1e-9; ssum += I[e]; }
        double ie = 0.0;
        for (int e = 0; e < 8; e++) {
            double q = I[e] / ssum;
            ie -= q * log(q + 1e-9);
        }
        double aux = el - 0.1 * (ie / log(8.0));
        aux_out[0] = (float)aux;
        for (int e = 0; e < 8; e++) g_flag[e] = flags[e];
    }
}

// ---------------------------------------------------------------------------
// Scatter into memset-zeroed disp/comb. 4 writes per token, no collisions.
// ---------------------------------------------------------------------------
__global__ __launch_bounds__(256)
void scatter_kernel(float* __restrict__ disp, float* __restrict__ comb)
{
    const int t = blockIdx.x * blockDim.x + threadIdx.x;
    if (t >= T_TOKENS) return;
    const int e1 = g_top1[t], e2 = g_top2[t];
    const int pos2 = g_flag[e2];
    const size_t base = (size_t)t * (E_EXP * CAP);
    disp[base + (size_t)e1 * CAP] = 1.0f;
    comb[base + (size_t)e1 * CAP] = g_p1[t];
    disp[base + (size_t)e2 * CAP + pos2] = 1.0f;
    comb[base + (size_t)e2 * CAP + pos2] = g_p2[t];
}

// ---------------------------------------------------------------------------
extern "C" void kernel_launch(void* const* d_in, const int* in_sizes, int n_in,
                              void* d_out, int out_size)
{
    const float* x   = (const float*)d_in[0];
    const float* Wi1 = (const float*)d_in[1];
    const float* bi1 = (const float*)d_in[2];
    const float* Wi2 = (const float*)d_in[3];
    const float* bi2 = (const float*)d_in[4];
    const float* Wr1 = (const float*)d_in[5];
    const float* br1 = (const float*)d_in[6];
    const float* Wr2 = (const float*)d_in[7];
    const float* br2 = (const float*)d_in[8];
    const float* Wu1 = (const float*)d_in[9];
    const float* bu1 = (const float*)d_in[10];
    const float* Wu2 = (const float*)d_in[11];
    const float* bu2 = (const float*)d_in[12];

    float* out = (float*)d_out;
    const size_t dispN = (size_t)T_TOKENS * E_EXP * CAP;
    float* disp  = out;
    float* comb  = out + dispN;
    float* probs = out + 2 * dispN;
    float* aux   = probs + (size_t)T_TOKENS * E_EXP;
    float* imp   = aux + 1;

    // Device addresses of compaction lists/counters
    int *d_listR = nullptr, *d_listU = nullptr, *d_cntR = nullptr, *d_cntU = nullptr;
    cudaGetSymbolAddress((void**)&d_listR, g_listR);
    cudaGetSymbolAddress((void**)&d_listU, g_listU);
    cudaGetSymbolAddress((void**)&d_cntR, g_cntR);
    cudaGetSymbolAddress((void**)&d_cntU, g_cntU);

    cudaMemsetAsync(d_out, 0, (size_t)out_size * sizeof(float));

    dim3 g1(1024 / 128, T_TOKENS / 128);     // 8 x 32
    gemm1_kernel<<<g1, 256>>>(x, Wi1, bi1);
    imp_kernel<<<T_TOKENS, 128>>>(Wi2, bi2, imp);

    dim3 g2(2048 / 128, T_TOKENS / 128);     // 16 x 32 (early exit past count)
    gemm2_kernel<<<g2, 256>>>(x, Wr1, br1, d_listR, d_cntR);
    gemm2_kernel<<<g2, 256>>>(x, Wu1, bu1, d_listU, d_cntU);

    router_kernel<<<T_TOKENS, 256>>>(Wr2, br2, Wu2, bu2, probs);
    reduce_aux_kernel<<<1, 256>>>(probs, aux);
    scatter_kernel<<<(T_TOKENS + 255) / 256, 256>>>(disp, comb);
}